// round 14
// baseline (speedup 1.0000x reference)
#include <cuda_runtime.h>
#include <math.h>
#include <stdint.h>

#define NSn 100000
#define NMn 50000
#define En  600000
#define Dn  128
#define HORn 8
#define NB  148          // persistent-kernel blocks (<= SM count, all co-resident)
#define NGB 8            // gate blocks (0..7)
#define SEQB 8           // sequencer block id
#define NWB (NB - 9)     // 139 worker blocks (9..147)
#define PTH 1024
#define TINYF 1.17549435e-38f

#ifndef RNG_MODE
#define RNG_MODE 0
#endif

// ---------------- scratch (device globals; no allocation allowed) ----------------
__device__ float    d_xl[(size_t)NSn * Dn];
__device__ float    d_xr[(size_t)NMn * Dn];
__device__ float    d_e[En];
__device__ float    d_s[NMn];
__device__ float    d_w[NSn];
__device__ float    d_v[Dn];
__device__ float    d_gum[(size_t)HORn * NMn];
__device__ float    d_pMs[HORn * NB], d_pSs[HORn * NB];
__device__ unsigned long long d_pKs[HORn * NB];
__device__ unsigned d_bar_cnt;
__device__ float    d_gates_g[HORn][4 * Dn];
__device__ float    d_hrelu_g[HORn][Dn];
__device__ unsigned d_gcnt[HORn];              // 8 gate-block arrivals
__device__ unsigned d_act[HORn];               // sampled action (sentinel 0xFFFFFFFF)
__device__ unsigned d_hflagv[HORn * NB * 8];   // per-block hrelu flag, 32B stride
__device__ unsigned d_donev[HORn * NB * 8];    // per-block done flag, 32B stride

// ---------------- f32x2 packed math helpers (Blackwell) ----------------
__device__ __forceinline__ unsigned long long ffma2(unsigned long long a,
                                                    unsigned long long b,
                                                    unsigned long long c) {
    unsigned long long d;
    asm("fma.rn.f32x2 %0, %1, %2, %3;" : "=l"(d) : "l"(a), "l"(b), "l"(c));
    return d;
}
__device__ __forceinline__ unsigned long long dup2(float x) {
    unsigned long long r;
    asm("mov.b64 %0, {%1, %1};" : "=l"(r) : "f"(x));
    return r;
}
__device__ __forceinline__ float2 unpack2(unsigned long long v) {
    float2 f;
    asm("mov.b64 {%0, %1}, %2;" : "=f"(f.x), "=f"(f.y) : "l"(v));
    return f;
}

// ---------------- threefry2x32 ----------------
__device__ __forceinline__ unsigned rotl32(unsigned x, int d) {
    return (x << d) | (x >> (32 - d));
}

__device__ __forceinline__ void tf2x32(unsigned k0, unsigned k1, unsigned c0, unsigned c1,
                                       unsigned& o0, unsigned& o1) {
    unsigned ks2 = k0 ^ k1 ^ 0x1BD11BDAu;
    unsigned x0 = c0 + k0, x1 = c1 + k1;
    const int ra[4] = {13, 15, 26, 6};
    const int rb[4] = {17, 29, 16, 24};
#pragma unroll
    for (int i = 0; i < 4; i++) { x0 += x1; x1 = rotl32(x1, ra[i]); x1 ^= x0; }
    x0 += k1; x1 += ks2 + 1u;
#pragma unroll
    for (int i = 0; i < 4; i++) { x0 += x1; x1 = rotl32(x1, rb[i]); x1 ^= x0; }
    x0 += ks2; x1 += k0 + 2u;
#pragma unroll
    for (int i = 0; i < 4; i++) { x0 += x1; x1 = rotl32(x1, ra[i]); x1 ^= x0; }
    x0 += k0; x1 += k1 + 3u;
#pragma unroll
    for (int i = 0; i < 4; i++) { x0 += x1; x1 = rotl32(x1, rb[i]); x1 ^= x0; }
    x0 += k1; x1 += ks2 + 4u;
#pragma unroll
    for (int i = 0; i < 4; i++) { x0 += x1; x1 = rotl32(x1, ra[i]); x1 ^= x0; }
    x0 += ks2; x1 += k0 + 5u;
    o0 = x0; o1 = x1;
}

// ---------------- setup: gumbel noise + zero all accumulators ----------------
__global__ void setup_kernel() {
    int idx = blockIdx.x * blockDim.x + threadIdx.x;

    if (idx < NMn) d_s[idx] = 0.0f;
    if (idx < NSn) d_w[idx] = 0.0f;
    if (idx < Dn) d_v[idx] = 0.0f;
    if (idx < HORn * NB * 8) { d_hflagv[idx] = 0u; d_donev[idx] = 0u; }
    if (idx < HORn) { d_gcnt[idx] = 0u; d_act[idx] = 0xFFFFFFFFu; }
    if (idx == 0) d_bar_cnt = 0u;

    if (idx >= HORn * NMn) return;
    int step = idx / NMn;
    int i = idx - step * NMn;

    unsigned k0, k1;
#if RNG_MODE == 0
    tf2x32(0u, 42u, 0u, (unsigned)step, k0, k1);
#elif RNG_MODE == 1
    { unsigned a0, a1, b0, b1;
      tf2x32(0u, 42u, 0u, (unsigned)(2 * step), a0, a1);     k0 = a0 ^ a1;
      tf2x32(0u, 42u, 0u, (unsigned)(2 * step + 1), b0, b1); k1 = b0 ^ b1; }
#else
    { unsigned t0 = (unsigned)(2 * step), t1 = (unsigned)(2 * step + 1);
      unsigned p0, p1, q0, q1;
      if (t0 < 8) { tf2x32(0u, 42u, t0, t0 + 8u, p0, p1); k0 = p0; }
      else        { tf2x32(0u, 42u, t0 - 8u, t0, p0, p1); k0 = p1; }
      if (t1 < 8) { tf2x32(0u, 42u, t1, t1 + 8u, q0, q1); k1 = q0; }
      else        { tf2x32(0u, 42u, t1 - 8u, t1, q0, q1); k1 = q1; } }
#endif

    unsigned bits;
#if RNG_MODE == 2
    { unsigned c = (i < NMn / 2) ? (unsigned)i : (unsigned)(i - NMn / 2);
      unsigned o0, o1;
      tf2x32(k0, k1, c, c + (unsigned)(NMn / 2), o0, o1);
      bits = (i < NMn / 2) ? o0 : o1; }
#else
    { unsigned o0, o1;
      tf2x32(k0, k1, 0u, (unsigned)i, o0, o1);
      bits = o0 ^ o1; }
#endif

    float u = __uint_as_float((bits >> 9) | 0x3f800000u) - 1.0f;
    u = u + TINYF;
    u = fmaxf(TINYF, u);
    d_gum[idx] = -logf(-logf(u));
}

// ---------------- float ordered-int helper ----------------
__device__ __forceinline__ unsigned ford(float f) {
    unsigned u = __float_as_uint(f);
    return (u & 0x80000000u) ? ~u : (u | 0x80000000u);
}

// ---------------- fused GEMM: xl = state*W_l^T  and  xr = model*W_r^T (f32x2 packed) ----------------
#define NBLK_NS ((NSn + 127) / 128)   // 782
#define NBLK_NM ((NMn + 127) / 128)   // 391

__global__ __launch_bounds__(256) void gemm_both(const float* __restrict__ state,
                                                 const float* __restrict__ model,
                                                 const float* __restrict__ W_l,
                                                 const float* __restrict__ W_r) {
    __shared__ __align__(16) float As[16][128];
    __shared__ __align__(16) float Ws[16][128];
    int tid = threadIdx.x;
    int tn = tid & 31, tm = tid >> 5;

    const float* A; const float* W; float* C; int N; int rowBase;
    if (blockIdx.x < NBLK_NS) {
        A = state; W = W_l; C = d_xl; N = NSn; rowBase = blockIdx.x * 128;
    } else {
        A = model; W = W_r; C = d_xr; N = NMn; rowBase = (blockIdx.x - NBLK_NS) * 128;
    }

    unsigned long long acc[8][4];
#pragma unroll
    for (int i = 0; i < 8; i++)
#pragma unroll
        for (int j = 0; j < 4; j++) acc[i][j] = 0ull;

    for (int k0 = 0; k0 < Dn; k0 += 16) {
#pragma unroll
        for (int r = 0; r < 2; r++) {
            int q = tid + 256 * r;
            int row = q >> 2; int kq = (q & 3) * 4;
            int ar = rowBase + row; if (ar >= N) ar = N - 1;
            float4 av = *(const float4*)(A + (size_t)ar * Dn + k0 + kq);
            As[kq + 0][row] = av.x; As[kq + 1][row] = av.y;
            As[kq + 2][row] = av.z; As[kq + 3][row] = av.w;
        }
#pragma unroll
        for (int r = 0; r < 2; r++) {
            int q = tid + 256 * r;
            int col = q >> 2; int kq = (q & 3) * 4;
            float4 wv = *(const float4*)(W + (size_t)col * Dn + k0 + kq);
            Ws[kq + 0][col] = wv.x; Ws[kq + 1][col] = wv.y;
            Ws[kq + 2][col] = wv.z; Ws[kq + 3][col] = wv.w;
        }
        __syncthreads();
#pragma unroll
        for (int kk = 0; kk < 16; kk++) {
            float4 bq = *(const float4*)&Ws[kk][tn * 4];
            unsigned long long bd0 = dup2(bq.x), bd1 = dup2(bq.y);
            unsigned long long bd2 = dup2(bq.z), bd3 = dup2(bq.w);
#pragma unroll
            for (int ip = 0; ip < 8; ip++) {
                unsigned long long a2 =
                    *(const unsigned long long*)&As[kk][tm * 16 + ip * 2];
                acc[ip][0] = ffma2(a2, bd0, acc[ip][0]);
                acc[ip][1] = ffma2(a2, bd1, acc[ip][1]);
                acc[ip][2] = ffma2(a2, bd2, acc[ip][2]);
                acc[ip][3] = ffma2(a2, bd3, acc[ip][3]);
            }
        }
        __syncthreads();
    }
#pragma unroll
    for (int ip = 0; ip < 8; ip++) {
        float2 c0 = unpack2(acc[ip][0]);
        float2 c1 = unpack2(acc[ip][1]);
        float2 c2 = unpack2(acc[ip][2]);
        float2 c3 = unpack2(acc[ip][3]);
        int r0 = rowBase + tm * 16 + ip * 2;
        if (r0 < N)
            *(float4*)(C + (size_t)r0 * Dn + tn * 4) = make_float4(c0.x, c1.x, c2.x, c3.x);
        if (r0 + 1 < N)
            *(float4*)(C + (size_t)(r0 + 1) * Dn + tn * 4) = make_float4(c0.y, c1.y, c2.y, c3.y);
    }
}

// ---------------- edge pass 1: warp per 4 edges (ILP), s[d] += exp(score) ----------------
__device__ __forceinline__ float lrelu_dot(float4 x, float4 y, float4 a) {
    float z, p = 0.0f;
    z = x.x + y.x; p += ((z > 0.f) ? z : 0.2f * z) * a.x;
    z = x.y + y.y; p += ((z > 0.f) ? z : 0.2f * z) * a.y;
    z = x.z + y.z; p += ((z > 0.f) ? z : 0.2f * z) * a.z;
    z = x.w + y.w; p += ((z > 0.f) ? z : 0.2f * z) * a.w;
    return p;
}

__global__ void edge_score_exp(const int* __restrict__ ei,
                               const float* __restrict__ att) {
    int lane = threadIdx.x & 31;
    int warp = (blockIdx.x * blockDim.x + threadIdx.x) >> 5;
    int nwarps = (gridDim.x * blockDim.x) >> 5;
    float4 a4 = ((const float4*)att)[lane];
    for (int base = warp * 4; base < En; base += nwarps * 4) {
        int s0 = ei[base + 0], s1 = ei[base + 1], s2 = ei[base + 2], s3 = ei[base + 3];
        int d0 = ei[En + base + 0], d1 = ei[En + base + 1];
        int d2 = ei[En + base + 2], d3 = ei[En + base + 3];
        float4 xl0 = ((const float4*)(d_xl + (size_t)s0 * Dn))[lane];
        float4 xl1 = ((const float4*)(d_xl + (size_t)s1 * Dn))[lane];
        float4 xl2 = ((const float4*)(d_xl + (size_t)s2 * Dn))[lane];
        float4 xl3 = ((const float4*)(d_xl + (size_t)s3 * Dn))[lane];
        float4 xr0 = ((const float4*)(d_xr + (size_t)d0 * Dn))[lane];
        float4 xr1 = ((const float4*)(d_xr + (size_t)d1 * Dn))[lane];
        float4 xr2 = ((const float4*)(d_xr + (size_t)d2 * Dn))[lane];
        float4 xr3 = ((const float4*)(d_xr + (size_t)d3 * Dn))[lane];
        float p0 = lrelu_dot(xl0, xr0, a4);
        float p1 = lrelu_dot(xl1, xr1, a4);
        float p2 = lrelu_dot(xl2, xr2, a4);
        float p3 = lrelu_dot(xl3, xr3, a4);
#pragma unroll
        for (int o = 16; o; o >>= 1) {
            p0 += __shfl_xor_sync(0xffffffffu, p0, o);
            p1 += __shfl_xor_sync(0xffffffffu, p1, o);
            p2 += __shfl_xor_sync(0xffffffffu, p2, o);
            p3 += __shfl_xor_sync(0xffffffffu, p3, o);
        }
        if (lane == 0) {
            float e0 = expf(p0), e1 = expf(p1), e2 = expf(p2), e3 = expf(p3);
            d_e[base + 0] = e0; d_e[base + 1] = e1;
            d_e[base + 2] = e2; d_e[base + 3] = e3;
            atomicAdd(&d_s[d0], e0);
            atomicAdd(&d_s[d1], e1);
            atomicAdd(&d_s[d2], e2);
            atomicAdd(&d_s[d3], e3);
        }
    }
}

// ---------------- persistent fused policy kernel ----------------
__device__ __forceinline__ float sigm(float x) { return 1.0f / (1.0f + expf(-x)); }

__device__ __forceinline__ void lse_merge(float& M, float& S, float M2, float S2) {
    if (M2 == -INFINITY) return;
    if (M == -INFINITY) { M = M2; S = S2; return; }
    if (M2 > M) { S = S * expf(M - M2) + S2; M = M2; }
    else        { S += S2 * expf(M2 - M); }
}

__device__ __forceinline__ void grid_sync(unsigned target) {
    __syncthreads();
    if (threadIdx.x == 0) {
        __threadfence();
        atomicAdd(&d_bar_cnt, 1u);
        while (*((volatile unsigned*)&d_bar_cnt) < target) { }
        __threadfence();
    }
    __syncthreads();
}

__global__ __launch_bounds__(PTH, 1) void policy_kernel(
    const int*   __restrict__ ei,
    const float* __restrict__ cbias,
    const float* __restrict__ Wih, const float* __restrict__ Whh,
    const float* __restrict__ bih, const float* __restrict__ bhh,
    const float* __restrict__ W1,  const float* __restrict__ b1,
    const float* __restrict__ W2,  const float* __restrict__ b2,
    const float* __restrict__ emb,
    float* __restrict__ out, int out_size)
{
    __shared__ __align__(16) float s_inp[Dn], s_h[Dn], s_c[Dn], s_hrelu[Dn];
    __shared__ float s_gates[4 * Dn];
    __shared__ __align__(16) float s_red[32 * Dn];
    __shared__ float s_wM[32], s_wS[32];
    __shared__ unsigned long long s_wK[32];
    __shared__ float s_cM, s_cS;
    __shared__ int   s_act;

    const int t = threadIdx.x;
    const int lane = t & 31;
    const int wib = t >> 5;
    const int b = blockIdx.x;
    unsigned bar = 0;

    // ---- prologue 0: w[src] += ex / s[dst] ----
    {
        int tg = b * PTH + t;
        int nth = NB * PTH;
        for (int e = tg; e < En; e += nth) {
            int s = ei[e];
            int d = ei[En + e];
            atomicAdd(&d_w[s], d_e[e] / d_s[d]);
        }
    }
    bar += NB; grid_sync(bar);

    // ---- prologue 1: v = sum_s w_s * xl[s] ----
    {
        int gw = b * 32 + wib;
        float4 acc = make_float4(0.f, 0.f, 0.f, 0.f);
        for (int s = gw; s < NSn; s += NB * 32) {
            float ws = d_w[s];
            if (ws != 0.0f) {
                float4 x = ((const float4*)(d_xl + (size_t)s * Dn))[lane];
                acc.x += ws * x.x; acc.y += ws * x.y;
                acc.z += ws * x.z; acc.w += ws * x.w;
            }
        }
        s_red[wib * Dn + lane * 4 + 0] = acc.x;
        s_red[wib * Dn + lane * 4 + 1] = acc.y;
        s_red[wib * Dn + lane * 4 + 2] = acc.z;
        s_red[wib * Dn + lane * 4 + 3] = acc.w;
        __syncthreads();
        if (t < Dn) {
            float v = 0.0f;
#pragma unroll
            for (int w = 0; w < 32; w++) v += s_red[w * Dn + t];
            atomicAdd(&d_v[t], v);
        }
    }
    bar += NB; grid_sync(bar);

    const int g8 = lane >> 3;
    const int l8 = lane & 7;
    const bool leader8 = (l8 == 0);

    if (b < NGB) {
        // ================= GATE BLOCKS 0..7 (64 gate rows each, L1-resident) =================
        if (t < Dn) {
            s_inp[t] = d_v[t] * (1.0f / (float)NMn) + cbias[t];
            s_h[t] = 0.0f; s_c[t] = 0.0f;
        }
        __syncthreads();
        const int rl = t >> 4;            // 0..63
        const int l16 = t & 15;
        const int r = (b << 6) + rl;      // 0..511
        const float4* wi = (const float4*)(Wih + (size_t)r * Dn);
        const float4* wh = (const float4*)(Whh + (size_t)r * Dn);

        for (int step = 0; step < HORn; step++) {
            // compute my 64 gate rows
            {
                const float4* pi = (const float4*)s_inp;
                const float4* ph = (const float4*)s_h;
                float a;
                {
                    float4 w4 = wi[l16];      float4 i4 = pi[l16];
                    a  = w4.x * i4.x + w4.y * i4.y + w4.z * i4.z + w4.w * i4.w;
                    float4 w5 = wi[l16 + 16]; float4 i5 = pi[l16 + 16];
                    a += w5.x * i5.x + w5.y * i5.y + w5.z * i5.z + w5.w * i5.w;
                    float4 v4 = wh[l16];      float4 h4 = ph[l16];
                    a += v4.x * h4.x + v4.y * h4.y + v4.z * h4.z + v4.w * h4.w;
                    float4 v5 = wh[l16 + 16]; float4 h5 = ph[l16 + 16];
                    a += v5.x * h5.x + v5.y * h5.y + v5.z * h5.z + v5.w * h5.w;
                }
                a += __shfl_xor_sync(0xffffffffu, a, 1);
                a += __shfl_xor_sync(0xffffffffu, a, 2);
                a += __shfl_xor_sync(0xffffffffu, a, 4);
                a += __shfl_xor_sync(0xffffffffu, a, 8);
                if (l16 == 0) d_gates_g[step][r] = a + bih[r] + bhh[r];
            }
            __syncthreads();
            if (t == 0) { __threadfence(); atomicAdd(&d_gcnt[step], 1u); }

            if (step == HORn - 1) break;   // nothing more needed from gate blocks

            // wait all 512 gates; replicated h,c update
            if (t == 0) {
                while (*((volatile unsigned*)&d_gcnt[step]) < NGB) { }
                __threadfence();
            }
            __syncthreads();
            if (t < 4 * Dn) s_gates[t] = d_gates_g[step][t];
            __syncthreads();
            if (t < Dn) {
                float ig = sigm(s_gates[t]);
                float fg = sigm(s_gates[Dn + t]);
                float gg = tanhf(s_gates[2 * Dn + t]);
                float og = sigm(s_gates[3 * Dn + t]);
                float c = fg * s_c[t] + ig * gg;
                s_c[t] = c;
                s_h[t] = og * tanhf(c);
            }
            // wait for sampled action, fetch next input
            if (t == 0) {
                unsigned a;
                while ((a = *((volatile unsigned*)&d_act[step])) == 0xFFFFFFFFu) { }
                s_act = (int)a;
            }
            __syncthreads();
            if (t < Dn) s_inp[t] = emb[(size_t)s_act * Dn + t];
            __syncthreads();
        }
    } else if (b == SEQB) {
        // ================= SEQUENCER BLOCK 8 (h,c + MLP1 + merge + sample) =================
        if (t < Dn) { s_h[t] = 0.0f; s_c[t] = 0.0f; }
        __syncthreads();

        for (int step = 0; step < HORn; step++) {
            // wait for gates
            if (t == 0) {
                while (*((volatile unsigned*)&d_gcnt[step]) < NGB) { }
                __threadfence();
            }
            __syncthreads();
            if (t < 4 * Dn) s_gates[t] = d_gates_g[step][t];
            __syncthreads();
            if (t < Dn) {
                float ig = sigm(s_gates[t]);
                float fg = sigm(s_gates[Dn + t]);
                float gg = tanhf(s_gates[2 * Dn + t]);
                float og = sigm(s_gates[3 * Dn + t]);
                float c = fg * s_c[t] + ig * gg;
                float h = og * tanhf(c);
                s_c[t] = c; s_h[t] = h;
            }
            __syncthreads();
            // MLP1 (8 threads/row, W1 L1-resident here)
            {
                int r = t >> 3;
                const float4* wr = (const float4*)(W1 + (size_t)r * Dn) + l8 * 4;
                const float4* ph = (const float4*)s_h + l8 * 4;
                float a = 0.0f;
#pragma unroll
                for (int k = 0; k < 4; k++) {
                    float4 w4 = wr[k]; float4 h4 = ph[k];
                    a += w4.x * h4.x + w4.y * h4.y + w4.z * h4.z + w4.w * h4.w;
                }
                a += __shfl_xor_sync(0xffffffffu, a, 1);
                a += __shfl_xor_sync(0xffffffffu, a, 2);
                a += __shfl_xor_sync(0xffffffffu, a, 4);
                if (l8 == 0) {
                    float hr = fmaxf(a + b1[r], 0.0f);
                    s_hrelu[r] = hr;
                    d_hrelu_g[step][r] = hr;
                }
            }
            __syncthreads();
            // raise 139 distributed worker flags
            if (t < NWB) {
                __threadfence();
                *((volatile unsigned*)&d_hflagv[(step * NB + 9 + t) * 8]) = 1u;
            }
            // poll worker done lines (distributed)
            if (wib == 0) {
                bool all = false;
                while (!all) {
                    unsigned got = 1u;
                    for (int i = 9 + lane; i < NB; i += 32)
                        got &= *((volatile unsigned*)&d_donev[(step * NB + i) * 8]);
                    all = __all_sync(0xffffffffu, got != 0u);
                }
                __threadfence();
            }
            __syncthreads();
            // merge partials + argmax (warp 0)
            if (wib == 0) {
                float M = -INFINITY, S = 0.0f;
                unsigned long long key = 0ull;
                for (int i = 9 + lane; i < NB; i += 32) {
                    lse_merge(M, S, d_pMs[step * NB + i], d_pSs[step * NB + i]);
                    unsigned long long k2 = d_pKs[step * NB + i];
                    if (k2 > key) key = k2;
                }
#pragma unroll
                for (int o = 16; o; o >>= 1) {
                    float M2 = __shfl_xor_sync(0xffffffffu, M, o);
                    float S2 = __shfl_xor_sync(0xffffffffu, S, o);
                    unsigned long long k2 = __shfl_xor_sync(0xffffffffu, key, o);
                    lse_merge(M, S, M2, S2);
                    if (k2 > key) key = k2;
                }
                if (lane == 0) {
                    int act = (int)(0xFFFFFFFFu - (unsigned)(key & 0xFFFFFFFFull));
                    s_act = act; s_cM = M; s_cS = S;
                    *((volatile unsigned*)&d_act[step]) = (unsigned)act;  // release to gate blocks
                }
            }
            __syncthreads();
            // output for this step (logit recompute on warp 0)
            if (wib == 0) {
                int act = s_act;
                const float4* wrow = (const float4*)(W2 + (size_t)act * Dn);
                const float4* hp = (const float4*)s_hrelu;
                float4 w4 = wrow[lane]; float4 h4 = hp[lane];
                float p = w4.x * h4.x + w4.y * h4.y + w4.z * h4.z + w4.w * h4.w;
#pragma unroll
                for (int o = 16; o; o >>= 1) p += __shfl_xor_sync(0xffffffffu, p, o);
                if (lane == 0) {
                    if (step < out_size) out[step] = (float)act;
                    if (8 + step < out_size)
                        out[8 + step] = (p + b2[act]) - (s_cM + logf(s_cS));
                }
            }
            __syncthreads();
        }
        // epilogue: final h, c
        if (t < Dn) {
            if (16 + t < out_size) out[16 + t] = s_h[t];
            if (144 + t < out_size) out[144 + t] = s_c[t];
        }
    } else {
        // ================= WORKER BLOCKS 9..147 (logits chunks) =================
        const int chunk = (NMn + NWB - 1) / NWB;      // 360
        const int row0 = (b - 9) * chunk;
        const int row1 = (row0 + chunk < NMn) ? (row0 + chunk) : NMn;

        for (int step = 0; step < HORn; step++) {
            if (t == 0) {
                while (*((volatile unsigned*)&d_hflagv[(step * NB + b) * 8]) == 0u) { }
                __threadfence();
            }
            __syncthreads();
            const float4* hg = (const float4*)d_hrelu_g[step];
            float4 h0 = hg[l8 * 4 + 0], h1 = hg[l8 * 4 + 1];
            float4 h2 = hg[l8 * 4 + 2], h3 = hg[l8 * 4 + 3];
            const float* gum = d_gum + (size_t)step * NMn;
            float M = -INFINITY, S = 0.0f;
            unsigned long long key = 0ull;

            for (int j = row0 + wib * 4; j < row1; j += 32 * 4) {
                int r = j + g8;
                float p = 0.0f;
                if (r < row1) {
                    const float4* wrow = (const float4*)(W2 + (size_t)r * Dn);
                    float4 w0 = wrow[l8 * 4 + 0], w1 = wrow[l8 * 4 + 1];
                    float4 w2 = wrow[l8 * 4 + 2], w3 = wrow[l8 * 4 + 3];
                    p  = w0.x * h0.x + w0.y * h0.y + w0.z * h0.z + w0.w * h0.w;
                    p += w1.x * h1.x + w1.y * h1.y + w1.z * h1.z + w1.w * h1.w;
                    p += w2.x * h2.x + w2.y * h2.y + w2.z * h2.z + w2.w * h2.w;
                    p += w3.x * h3.x + w3.y * h3.y + w3.z * h3.z + w3.w * h3.w;
                }
                p += __shfl_xor_sync(0xffffffffu, p, 1);
                p += __shfl_xor_sync(0xffffffffu, p, 2);
                p += __shfl_xor_sync(0xffffffffu, p, 4);
                if (leader8 && r < row1) {
                    float l = p + b2[r];
                    if (l > M) { S = S * expf(M - l) + 1.0f; M = l; }
                    else       { S += expf(l - M); }
                    float v = l + gum[r];
                    unsigned long long k2 =
                        ((unsigned long long)ford(v) << 32) | (0xFFFFFFFFu - (unsigned)r);
                    if (k2 > key) key = k2;
                }
            }
#pragma unroll
            for (int o = 16; o; o >>= 1) {
                float M2 = __shfl_xor_sync(0xffffffffu, M, o);
                float S2 = __shfl_xor_sync(0xffffffffu, S, o);
                unsigned long long k2 = __shfl_xor_sync(0xffffffffu, key, o);
                lse_merge(M, S, M2, S2);
                if (k2 > key) key = k2;
            }
            if (lane == 0) { s_wM[wib] = M; s_wS[wib] = S; s_wK[wib] = key; }
            __syncthreads();
            if (wib == 0) {
                M = s_wM[lane]; S = s_wS[lane]; key = s_wK[lane];
#pragma unroll
                for (int o = 16; o; o >>= 1) {
                    float M2 = __shfl_xor_sync(0xffffffffu, M, o);
                    float S2 = __shfl_xor_sync(0xffffffffu, S, o);
                    unsigned long long k2 = __shfl_xor_sync(0xffffffffu, key, o);
                    lse_merge(M, S, M2, S2);
                    if (k2 > key) key = k2;
                }
                if (lane == 0) {
                    d_pMs[step * NB + b] = M;
                    d_pSs[step * NB + b] = S;
                    d_pKs[step * NB + b] = key;
                    __threadfence();
                    *((volatile unsigned*)&d_donev[(step * NB + b) * 8]) = 1u;
                }
            }
        }
    }
}

// ---------------- host launcher ----------------
extern "C" void kernel_launch(void* const* d_in, const int* in_sizes, int n_in,
                              void* d_out, int out_size) {
    const float* state = (const float*)d_in[0];
    const float* model = (const float*)d_in[1];
    const int*   ei    = (const int*)d_in[2];
    const float* W_l   = (const float*)d_in[3];
    const float* W_r   = (const float*)d_in[4];
    const float* att   = (const float*)d_in[5];
    const float* cbias = (const float*)d_in[6];
    const float* Wih   = (const float*)d_in[7];
    const float* Whh   = (const float*)d_in[8];
    const float* bih   = (const float*)d_in[9];
    const float* bhh   = (const float*)d_in[10];
    const float* pW1   = (const float*)d_in[11];
    const float* pb1   = (const float*)d_in[12];
    const float* pW2   = (const float*)d_in[13];
    const float* pb2   = (const float*)d_in[14];
    const float* emb   = (const float*)d_in[15];
    float* out = (float*)d_out;

    setup_kernel<<<(HORn * NMn + 255) / 256, 256>>>();
    gemm_both<<<NBLK_NS + NBLK_NM, 256>>>(state, model, W_l, W_r);
    edge_score_exp<<<2048, 256>>>(ei, att);
    policy_kernel<<<NB, PTH>>>(ei, cbias, Wih, Whh, bih, bhh,
                               pW1, pb1, pW2, pb2, emb, out, out_size);
}

// round 15
// speedup vs baseline: 1.1155x; 1.1155x over previous
#include <cuda_runtime.h>
#include <math.h>
#include <stdint.h>

#define NSn 100000
#define NMn 50000
#define En  600000
#define Dn  128
#define HORn 8
#define NB  148          // persistent-kernel blocks (<= SM count, all co-resident)
#define NGB 8            // gate blocks (0..7)
#define SEQB 8           // sequencer block id (off critical path)
#define NWB (NB - 9)     // 139 worker blocks (9..147)
#define PTH 1024
#define TINYF 1.17549435e-38f

#ifndef RNG_MODE
#define RNG_MODE 0
#endif

// ---------------- scratch (device globals; no allocation allowed) ----------------
__device__ float    d_xl[(size_t)NSn * Dn];
__device__ float    d_xr[(size_t)NMn * Dn];
__device__ float    d_e[En];
__device__ float    d_s[NMn];
__device__ float    d_w[NSn];
__device__ float    d_v[Dn];
__device__ float    d_gum[(size_t)HORn * NMn];
__device__ float    d_pMs[HORn * NB], d_pSs[HORn * NB];
__device__ unsigned long long d_pKs[HORn * NB];
__device__ unsigned d_bar_cnt;
__device__ float    d_gates_g[HORn][4 * Dn];
__device__ unsigned d_gcnt[HORn];              // 8 gate-block arrivals
__device__ unsigned d_donev[HORn * NB * 8];    // per-block done flag, 32B stride

// ---------------- f32x2 packed math helpers (Blackwell) ----------------
__device__ __forceinline__ unsigned long long ffma2(unsigned long long a,
                                                    unsigned long long b,
                                                    unsigned long long c) {
    unsigned long long d;
    asm("fma.rn.f32x2 %0, %1, %2, %3;" : "=l"(d) : "l"(a), "l"(b), "l"(c));
    return d;
}
__device__ __forceinline__ unsigned long long dup2(float x) {
    unsigned long long r;
    asm("mov.b64 %0, {%1, %1};" : "=l"(r) : "f"(x));
    return r;
}
__device__ __forceinline__ float2 unpack2(unsigned long long v) {
    float2 f;
    asm("mov.b64 {%0, %1}, %2;" : "=f"(f.x), "=f"(f.y) : "l"(v));
    return f;
}

// ---------------- threefry2x32 ----------------
__device__ __forceinline__ unsigned rotl32(unsigned x, int d) {
    return (x << d) | (x >> (32 - d));
}

__device__ __forceinline__ void tf2x32(unsigned k0, unsigned k1, unsigned c0, unsigned c1,
                                       unsigned& o0, unsigned& o1) {
    unsigned ks2 = k0 ^ k1 ^ 0x1BD11BDAu;
    unsigned x0 = c0 + k0, x1 = c1 + k1;
    const int ra[4] = {13, 15, 26, 6};
    const int rb[4] = {17, 29, 16, 24};
#pragma unroll
    for (int i = 0; i < 4; i++) { x0 += x1; x1 = rotl32(x1, ra[i]); x1 ^= x0; }
    x0 += k1; x1 += ks2 + 1u;
#pragma unroll
    for (int i = 0; i < 4; i++) { x0 += x1; x1 = rotl32(x1, rb[i]); x1 ^= x0; }
    x0 += ks2; x1 += k0 + 2u;
#pragma unroll
    for (int i = 0; i < 4; i++) { x0 += x1; x1 = rotl32(x1, ra[i]); x1 ^= x0; }
    x0 += k0; x1 += k1 + 3u;
#pragma unroll
    for (int i = 0; i < 4; i++) { x0 += x1; x1 = rotl32(x1, rb[i]); x1 ^= x0; }
    x0 += k1; x1 += ks2 + 4u;
#pragma unroll
    for (int i = 0; i < 4; i++) { x0 += x1; x1 = rotl32(x1, ra[i]); x1 ^= x0; }
    x0 += ks2; x1 += k0 + 5u;
    o0 = x0; o1 = x1;
}

// ---------------- setup: gumbel noise + zero all accumulators ----------------
__global__ void setup_kernel() {
    int idx = blockIdx.x * blockDim.x + threadIdx.x;

    if (idx < NMn) d_s[idx] = 0.0f;
    if (idx < NSn) d_w[idx] = 0.0f;
    if (idx < Dn) d_v[idx] = 0.0f;
    if (idx < HORn * NB * 8) d_donev[idx] = 0u;
    if (idx < HORn) d_gcnt[idx] = 0u;
    if (idx == 0) d_bar_cnt = 0u;

    if (idx >= HORn * NMn) return;
    int step = idx / NMn;
    int i = idx - step * NMn;

    unsigned k0, k1;
#if RNG_MODE == 0
    tf2x32(0u, 42u, 0u, (unsigned)step, k0, k1);
#elif RNG_MODE == 1
    { unsigned a0, a1, b0, b1;
      tf2x32(0u, 42u, 0u, (unsigned)(2 * step), a0, a1);     k0 = a0 ^ a1;
      tf2x32(0u, 42u, 0u, (unsigned)(2 * step + 1), b0, b1); k1 = b0 ^ b1; }
#else
    { unsigned t0 = (unsigned)(2 * step), t1 = (unsigned)(2 * step + 1);
      unsigned p0, p1, q0, q1;
      if (t0 < 8) { tf2x32(0u, 42u, t0, t0 + 8u, p0, p1); k0 = p0; }
      else        { tf2x32(0u, 42u, t0 - 8u, t0, p0, p1); k0 = p1; }
      if (t1 < 8) { tf2x32(0u, 42u, t1, t1 + 8u, q0, q1); k1 = q0; }
      else        { tf2x32(0u, 42u, t1 - 8u, t1, q0, q1); k1 = q1; } }
#endif

    unsigned bits;
#if RNG_MODE == 2
    { unsigned c = (i < NMn / 2) ? (unsigned)i : (unsigned)(i - NMn / 2);
      unsigned o0, o1;
      tf2x32(k0, k1, c, c + (unsigned)(NMn / 2), o0, o1);
      bits = (i < NMn / 2) ? o0 : o1; }
#else
    { unsigned o0, o1;
      tf2x32(k0, k1, 0u, (unsigned)i, o0, o1);
      bits = o0 ^ o1; }
#endif

    float u = __uint_as_float((bits >> 9) | 0x3f800000u) - 1.0f;
    u = u + TINYF;
    u = fmaxf(TINYF, u);
    d_gum[idx] = -logf(-logf(u));
}

// ---------------- float ordered-int helper ----------------
__device__ __forceinline__ unsigned ford(float f) {
    unsigned u = __float_as_uint(f);
    return (u & 0x80000000u) ? ~u : (u | 0x80000000u);
}

// ---------------- fused GEMM: xl = state*W_l^T  and  xr = model*W_r^T (f32x2 packed) ----------------
#define NBLK_NS ((NSn + 127) / 128)   // 782
#define NBLK_NM ((NMn + 127) / 128)   // 391

__global__ __launch_bounds__(256) void gemm_both(const float* __restrict__ state,
                                                 const float* __restrict__ model,
                                                 const float* __restrict__ W_l,
                                                 const float* __restrict__ W_r) {
    __shared__ __align__(16) float As[16][128];
    __shared__ __align__(16) float Ws[16][128];
    int tid = threadIdx.x;
    int tn = tid & 31, tm = tid >> 5;

    const float* A; const float* W; float* C; int N; int rowBase;
    if (blockIdx.x < NBLK_NS) {
        A = state; W = W_l; C = d_xl; N = NSn; rowBase = blockIdx.x * 128;
    } else {
        A = model; W = W_r; C = d_xr; N = NMn; rowBase = (blockIdx.x - NBLK_NS) * 128;
    }

    unsigned long long acc[8][4];
#pragma unroll
    for (int i = 0; i < 8; i++)
#pragma unroll
        for (int j = 0; j < 4; j++) acc[i][j] = 0ull;

    for (int k0 = 0; k0 < Dn; k0 += 16) {
#pragma unroll
        for (int r = 0; r < 2; r++) {
            int q = tid + 256 * r;
            int row = q >> 2; int kq = (q & 3) * 4;
            int ar = rowBase + row; if (ar >= N) ar = N - 1;
            float4 av = *(const float4*)(A + (size_t)ar * Dn + k0 + kq);
            As[kq + 0][row] = av.x; As[kq + 1][row] = av.y;
            As[kq + 2][row] = av.z; As[kq + 3][row] = av.w;
        }
#pragma unroll
        for (int r = 0; r < 2; r++) {
            int q = tid + 256 * r;
            int col = q >> 2; int kq = (q & 3) * 4;
            float4 wv = *(const float4*)(W + (size_t)col * Dn + k0 + kq);
            Ws[kq + 0][col] = wv.x; Ws[kq + 1][col] = wv.y;
            Ws[kq + 2][col] = wv.z; Ws[kq + 3][col] = wv.w;
        }
        __syncthreads();
#pragma unroll
        for (int kk = 0; kk < 16; kk++) {
            float4 bq = *(const float4*)&Ws[kk][tn * 4];
            unsigned long long bd0 = dup2(bq.x), bd1 = dup2(bq.y);
            unsigned long long bd2 = dup2(bq.z), bd3 = dup2(bq.w);
#pragma unroll
            for (int ip = 0; ip < 8; ip++) {
                unsigned long long a2 =
                    *(const unsigned long long*)&As[kk][tm * 16 + ip * 2];
                acc[ip][0] = ffma2(a2, bd0, acc[ip][0]);
                acc[ip][1] = ffma2(a2, bd1, acc[ip][1]);
                acc[ip][2] = ffma2(a2, bd2, acc[ip][2]);
                acc[ip][3] = ffma2(a2, bd3, acc[ip][3]);
            }
        }
        __syncthreads();
    }
#pragma unroll
    for (int ip = 0; ip < 8; ip++) {
        float2 c0 = unpack2(acc[ip][0]);
        float2 c1 = unpack2(acc[ip][1]);
        float2 c2 = unpack2(acc[ip][2]);
        float2 c3 = unpack2(acc[ip][3]);
        int r0 = rowBase + tm * 16 + ip * 2;
        if (r0 < N)
            *(float4*)(C + (size_t)r0 * Dn + tn * 4) = make_float4(c0.x, c1.x, c2.x, c3.x);
        if (r0 + 1 < N)
            *(float4*)(C + (size_t)(r0 + 1) * Dn + tn * 4) = make_float4(c0.y, c1.y, c2.y, c3.y);
    }
}

// ---------------- edge pass 1: warp per 4 edges (ILP), s[d] += exp(score) ----------------
__device__ __forceinline__ float lrelu_dot(float4 x, float4 y, float4 a) {
    float z, p = 0.0f;
    z = x.x + y.x; p += ((z > 0.f) ? z : 0.2f * z) * a.x;
    z = x.y + y.y; p += ((z > 0.f) ? z : 0.2f * z) * a.y;
    z = x.z + y.z; p += ((z > 0.f) ? z : 0.2f * z) * a.z;
    z = x.w + y.w; p += ((z > 0.f) ? z : 0.2f * z) * a.w;
    return p;
}

__global__ void edge_score_exp(const int* __restrict__ ei,
                               const float* __restrict__ att) {
    int lane = threadIdx.x & 31;
    int warp = (blockIdx.x * blockDim.x + threadIdx.x) >> 5;
    int nwarps = (gridDim.x * blockDim.x) >> 5;
    float4 a4 = ((const float4*)att)[lane];
    for (int base = warp * 4; base < En; base += nwarps * 4) {
        int s0 = ei[base + 0], s1 = ei[base + 1], s2 = ei[base + 2], s3 = ei[base + 3];
        int d0 = ei[En + base + 0], d1 = ei[En + base + 1];
        int d2 = ei[En + base + 2], d3 = ei[En + base + 3];
        float4 xl0 = ((const float4*)(d_xl + (size_t)s0 * Dn))[lane];
        float4 xl1 = ((const float4*)(d_xl + (size_t)s1 * Dn))[lane];
        float4 xl2 = ((const float4*)(d_xl + (size_t)s2 * Dn))[lane];
        float4 xl3 = ((const float4*)(d_xl + (size_t)s3 * Dn))[lane];
        float4 xr0 = ((const float4*)(d_xr + (size_t)d0 * Dn))[lane];
        float4 xr1 = ((const float4*)(d_xr + (size_t)d1 * Dn))[lane];
        float4 xr2 = ((const float4*)(d_xr + (size_t)d2 * Dn))[lane];
        float4 xr3 = ((const float4*)(d_xr + (size_t)d3 * Dn))[lane];
        float p0 = lrelu_dot(xl0, xr0, a4);
        float p1 = lrelu_dot(xl1, xr1, a4);
        float p2 = lrelu_dot(xl2, xr2, a4);
        float p3 = lrelu_dot(xl3, xr3, a4);
#pragma unroll
        for (int o = 16; o; o >>= 1) {
            p0 += __shfl_xor_sync(0xffffffffu, p0, o);
            p1 += __shfl_xor_sync(0xffffffffu, p1, o);
            p2 += __shfl_xor_sync(0xffffffffu, p2, o);
            p3 += __shfl_xor_sync(0xffffffffu, p3, o);
        }
        if (lane == 0) {
            float e0 = expf(p0), e1 = expf(p1), e2 = expf(p2), e3 = expf(p3);
            d_e[base + 0] = e0; d_e[base + 1] = e1;
            d_e[base + 2] = e2; d_e[base + 3] = e3;
            atomicAdd(&d_s[d0], e0);
            atomicAdd(&d_s[d1], e1);
            atomicAdd(&d_s[d2], e2);
            atomicAdd(&d_s[d3], e3);
        }
    }
}

// ---------------- persistent fused policy kernel ----------------
__device__ __forceinline__ float sigm(float x) { return 1.0f / (1.0f + expf(-x)); }

__device__ __forceinline__ void lse_merge(float& M, float& S, float M2, float S2) {
    if (M2 == -INFINITY) return;
    if (M == -INFINITY) { M = M2; S = S2; return; }
    if (M2 > M) { S = S * expf(M - M2) + S2; M = M2; }
    else        { S += S2 * expf(M2 - M); }
}

__device__ __forceinline__ void grid_sync(unsigned target) {
    __syncthreads();
    if (threadIdx.x == 0) {
        __threadfence();
        atomicAdd(&d_bar_cnt, 1u);
        while (*((volatile unsigned*)&d_bar_cnt) < target) { }
        __threadfence();
    }
    __syncthreads();
}

// sweep all worker done-lines for a step (call from one warp), then fence
__device__ __forceinline__ void sweep_done(int step, int lane) {
    bool all = false;
    while (!all) {
        unsigned got = 1u;
        for (int i = 9 + lane; i < NB; i += 32)
            got &= *((volatile unsigned*)&d_donev[(step * NB + i) * 8]);
        all = __all_sync(0xffffffffu, got != 0u);
    }
    __threadfence();
}

// max over worker keys (one warp); returns key on lane 0
__device__ __forceinline__ unsigned long long merge_keys(int step, int lane) {
    unsigned long long key = 0ull;
    for (int i = 9 + lane; i < NB; i += 32) {
        unsigned long long k2 = d_pKs[step * NB + i];
        if (k2 > key) key = k2;
    }
#pragma unroll
    for (int o = 16; o; o >>= 1) {
        unsigned long long k2 = __shfl_xor_sync(0xffffffffu, key, o);
        if (k2 > key) key = k2;
    }
    return key;
}

__global__ __launch_bounds__(PTH, 1) void policy_kernel(
    const int*   __restrict__ ei,
    const float* __restrict__ cbias,
    const float* __restrict__ Wih, const float* __restrict__ Whh,
    const float* __restrict__ bih, const float* __restrict__ bhh,
    const float* __restrict__ W1,  const float* __restrict__ b1,
    const float* __restrict__ W2,  const float* __restrict__ b2,
    const float* __restrict__ emb,
    float* __restrict__ out, int out_size)
{
    __shared__ __align__(16) float s_inp[Dn], s_h[Dn], s_c[Dn], s_hrelu[Dn];
    __shared__ float s_gates[4 * Dn];
    __shared__ __align__(16) float s_red[32 * Dn];
    __shared__ float s_wM[32], s_wS[32];
    __shared__ unsigned long long s_wK[32];
    __shared__ float s_cM, s_cS;
    __shared__ int   s_act;

    const int t = threadIdx.x;
    const int lane = t & 31;
    const int wib = t >> 5;
    const int b = blockIdx.x;
    unsigned bar = 0;

    // ---- prologue 0: w[src] += ex / s[dst] ----
    {
        int tg = b * PTH + t;
        int nth = NB * PTH;
        for (int e = tg; e < En; e += nth) {
            int s = ei[e];
            int d = ei[En + e];
            atomicAdd(&d_w[s], d_e[e] / d_s[d]);
        }
    }
    bar += NB; grid_sync(bar);

    // ---- prologue 1: v = sum_s w_s * xl[s] ----
    {
        int gw = b * 32 + wib;
        float4 acc = make_float4(0.f, 0.f, 0.f, 0.f);
        for (int s = gw; s < NSn; s += NB * 32) {
            float ws = d_w[s];
            if (ws != 0.0f) {
                float4 x = ((const float4*)(d_xl + (size_t)s * Dn))[lane];
                acc.x += ws * x.x; acc.y += ws * x.y;
                acc.z += ws * x.z; acc.w += ws * x.w;
            }
        }
        s_red[wib * Dn + lane * 4 + 0] = acc.x;
        s_red[wib * Dn + lane * 4 + 1] = acc.y;
        s_red[wib * Dn + lane * 4 + 2] = acc.z;
        s_red[wib * Dn + lane * 4 + 3] = acc.w;
        __syncthreads();
        if (t < Dn) {
            float v = 0.0f;
#pragma unroll
            for (int w = 0; w < 32; w++) v += s_red[w * Dn + t];
            atomicAdd(&d_v[t], v);
        }
    }
    bar += NB; grid_sync(bar);

    const int g8 = lane >> 3;
    const int l8 = lane & 7;
    const bool leader8 = (l8 == 0);

    // All roles start with identical inp=g, h=c=0
    if (t < Dn) {
        s_inp[t] = d_v[t] * (1.0f / (float)NMn) + cbias[t];
        s_h[t] = 0.0f; s_c[t] = 0.0f;
    }
    __syncthreads();

    if (b < NGB) {
        // ============ GATE BLOCKS 0..7 (64 gate rows each, weights L1-resident) ============
        const int rl = t >> 4;            // 0..63
        const int l16 = t & 15;
        const int r = (b << 6) + rl;      // 0..511
        const float4* wi = (const float4*)(Wih + (size_t)r * Dn);
        const float4* wh = (const float4*)(Whh + (size_t)r * Dn);

        for (int step = 0; step < HORn; step++) {
            // compute my 64 gate rows
            {
                const float4* pi = (const float4*)s_inp;
                const float4* ph = (const float4*)s_h;
                float a;
                {
                    float4 w4 = wi[l16];      float4 i4 = pi[l16];
                    a  = w4.x * i4.x + w4.y * i4.y + w4.z * i4.z + w4.w * i4.w;
                    float4 w5 = wi[l16 + 16]; float4 i5 = pi[l16 + 16];
                    a += w5.x * i5.x + w5.y * i5.y + w5.z * i5.z + w5.w * i5.w;
                    float4 v4 = wh[l16];      float4 h4 = ph[l16];
                    a += v4.x * h4.x + v4.y * h4.y + v4.z * h4.z + v4.w * h4.w;
                    float4 v5 = wh[l16 + 16]; float4 h5 = ph[l16 + 16];
                    a += v5.x * h5.x + v5.y * h5.y + v5.z * h5.z + v5.w * h5.w;
                }
                a += __shfl_xor_sync(0xffffffffu, a, 1);
                a += __shfl_xor_sync(0xffffffffu, a, 2);
                a += __shfl_xor_sync(0xffffffffu, a, 4);
                a += __shfl_xor_sync(0xffffffffu, a, 8);
                if (l16 == 0) d_gates_g[step][r] = a + bih[r] + bhh[r];
            }
            __syncthreads();
            if (t == 0) { __threadfence(); atomicAdd(&d_gcnt[step], 1u); }

            if (step == HORn - 1) break;

            // wait for workers of this step (implies gates complete), get act via keys
            if (wib == 0) {
                sweep_done(step, lane);
                unsigned long long key = merge_keys(step, lane);
                if (lane == 0) s_act = (int)(0xFFFFFFFFu - (unsigned)(key & 0xFFFFFFFFull));
            }
            __syncthreads();
            // update h,c from full gate vector; next input = emb[act]
            if (t < 4 * Dn) s_gates[t] = d_gates_g[step][t];
            __syncthreads();
            if (t < Dn) {
                float ig = sigm(s_gates[t]);
                float fg = sigm(s_gates[Dn + t]);
                float gg = tanhf(s_gates[2 * Dn + t]);
                float og = sigm(s_gates[3 * Dn + t]);
                float c = fg * s_c[t] + ig * gg;
                s_c[t] = c;
                s_h[t] = og * tanhf(c);
                s_inp[t] = emb[(size_t)s_act * Dn + t];
            }
            __syncthreads();
        }
    } else if (b == SEQB) {
        // ============ SEQUENCER BLOCK 8 (outputs only; off critical path) ============
        for (int step = 0; step < HORn; step++) {
            // wait for workers; merge lse + argmax
            if (wib == 0) {
                sweep_done(step, lane);
                float M = -INFINITY, S = 0.0f;
                unsigned long long key = 0ull;
                for (int i = 9 + lane; i < NB; i += 32) {
                    lse_merge(M, S, d_pMs[step * NB + i], d_pSs[step * NB + i]);
                    unsigned long long k2 = d_pKs[step * NB + i];
                    if (k2 > key) key = k2;
                }
#pragma unroll
                for (int o = 16; o; o >>= 1) {
                    float M2 = __shfl_xor_sync(0xffffffffu, M, o);
                    float S2 = __shfl_xor_sync(0xffffffffu, S, o);
                    unsigned long long k2 = __shfl_xor_sync(0xffffffffu, key, o);
                    lse_merge(M, S, M2, S2);
                    if (k2 > key) key = k2;
                }
                if (lane == 0) {
                    s_act = (int)(0xFFFFFFFFu - (unsigned)(key & 0xFFFFFFFFull));
                    s_cM = M; s_cS = S;
                }
            }
            __syncthreads();
            // own h,c + hrelu (gates are complete because workers finished)
            if (t < 4 * Dn) s_gates[t] = d_gates_g[step][t];
            __syncthreads();
            if (t < Dn) {
                float ig = sigm(s_gates[t]);
                float fg = sigm(s_gates[Dn + t]);
                float gg = tanhf(s_gates[2 * Dn + t]);
                float og = sigm(s_gates[3 * Dn + t]);
                float c = fg * s_c[t] + ig * gg;
                float h = og * tanhf(c);
                s_c[t] = c; s_h[t] = h;
            }
            __syncthreads();
            {
                int r = t >> 3;
                const float4* wr = (const float4*)(W1 + (size_t)r * Dn) + l8 * 4;
                const float4* ph = (const float4*)s_h + l8 * 4;
                float a = 0.0f;
#pragma unroll
                for (int k = 0; k < 4; k++) {
                    float4 w4 = wr[k]; float4 h4 = ph[k];
                    a += w4.x * h4.x + w4.y * h4.y + w4.z * h4.z + w4.w * h4.w;
                }
                a += __shfl_xor_sync(0xffffffffu, a, 1);
                a += __shfl_xor_sync(0xffffffffu, a, 2);
                a += __shfl_xor_sync(0xffffffffu, a, 4);
                if (l8 == 0) s_hrelu[r] = fmaxf(a + b1[r], 0.0f);
            }
            __syncthreads();
            // outputs (logit recompute on warp 0)
            if (wib == 0) {
                int act = s_act;
                const float4* wrow = (const float4*)(W2 + (size_t)act * Dn);
                const float4* hp = (const float4*)s_hrelu;
                float4 w4 = wrow[lane]; float4 h4 = hp[lane];
                float p = w4.x * h4.x + w4.y * h4.y + w4.z * h4.z + w4.w * h4.w;
#pragma unroll
                for (int o = 16; o; o >>= 1) p += __shfl_xor_sync(0xffffffffu, p, o);
                if (lane == 0) {
                    if (step < out_size) out[step] = (float)act;
                    if (8 + step < out_size)
                        out[8 + step] = (p + b2[act]) - (s_cM + logf(s_cS));
                }
            }
            __syncthreads();
        }
        // epilogue: final h, c
        if (t < Dn) {
            if (16 + t < out_size) out[16 + t] = s_h[t];
            if (144 + t < out_size) out[144 + t] = s_c[t];
        }
    } else {
        // ============ WORKER BLOCKS 9..147 (replicated h,c + MLP1; logits chunk) ============
        const int chunk = (NMn + NWB - 1) / NWB;      // 360
        const int row0 = (b - 9) * chunk;
        const int row1 = (row0 + chunk < NMn) ? (row0 + chunk) : NMn;

        for (int step = 0; step < HORn; step++) {
            // wait for all 512 gates (read-only poll of one word)
            if (t == 0) {
                while (*((volatile unsigned*)&d_gcnt[step]) < NGB) { }
                __threadfence();
            }
            __syncthreads();
            if (t < 4 * Dn) s_gates[t] = d_gates_g[step][t];
            __syncthreads();
            if (t < Dn) {
                float ig = sigm(s_gates[t]);
                float fg = sigm(s_gates[Dn + t]);
                float gg = tanhf(s_gates[2 * Dn + t]);
                float og = sigm(s_gates[3 * Dn + t]);
                float c = fg * s_c[t] + ig * gg;
                float h = og * tanhf(c);
                s_c[t] = c; s_h[t] = h;
            }
            __syncthreads();
            // MLP1 replicated (8 threads/row)
            {
                int r = t >> 3;
                const float4* wr = (const float4*)(W1 + (size_t)r * Dn) + l8 * 4;
                const float4* ph = (const float4*)s_h + l8 * 4;
                float a = 0.0f;
#pragma unroll
                for (int k = 0; k < 4; k++) {
                    float4 w4 = wr[k]; float4 h4 = ph[k];
                    a += w4.x * h4.x + w4.y * h4.y + w4.z * h4.z + w4.w * h4.w;
                }
                a += __shfl_xor_sync(0xffffffffu, a, 1);
                a += __shfl_xor_sync(0xffffffffu, a, 2);
                a += __shfl_xor_sync(0xffffffffu, a, 4);
                if (l8 == 0) s_hrelu[r] = fmaxf(a + b1[r], 0.0f);
            }
            __syncthreads();

            // phase B: logits chunk + online lse + argmax
            const float4* hp = (const float4*)s_hrelu;
            float4 h0 = hp[l8 * 4 + 0], h1 = hp[l8 * 4 + 1];
            float4 h2 = hp[l8 * 4 + 2], h3 = hp[l8 * 4 + 3];
            const float* gum = d_gum + (size_t)step * NMn;
            float M = -INFINITY, S = 0.0f;
            unsigned long long key = 0ull;

            for (int j = row0 + wib * 4; j < row1; j += 32 * 4) {
                int r = j + g8;
                float p = 0.0f;
                if (r < row1) {
                    const float4* wrow = (const float4*)(W2 + (size_t)r * Dn);
                    float4 w0 = wrow[l8 * 4 + 0], w1 = wrow[l8 * 4 + 1];
                    float4 w2 = wrow[l8 * 4 + 2], w3 = wrow[l8 * 4 + 3];
                    p  = w0.x * h0.x + w0.y * h0.y + w0.z * h0.z + w0.w * h0.w;
                    p += w1.x * h1.x + w1.y * h1.y + w1.z * h1.z + w1.w * h1.w;
                    p += w2.x * h2.x + w2.y * h2.y + w2.z * h2.z + w2.w * h2.w;
                    p += w3.x * h3.x + w3.y * h3.y + w3.z * h3.z + w3.w * h3.w;
                }
                p += __shfl_xor_sync(0xffffffffu, p, 1);
                p += __shfl_xor_sync(0xffffffffu, p, 2);
                p += __shfl_xor_sync(0xffffffffu, p, 4);
                if (leader8 && r < row1) {
                    float l = p + b2[r];
                    if (l > M) { S = S * expf(M - l) + 1.0f; M = l; }
                    else       { S += expf(l - M); }
                    float v = l + gum[r];
                    unsigned long long k2 =
                        ((unsigned long long)ford(v) << 32) | (0xFFFFFFFFu - (unsigned)r);
                    if (k2 > key) key = k2;
                }
            }
#pragma unroll
            for (int o = 16; o; o >>= 1) {
                float M2 = __shfl_xor_sync(0xffffffffu, M, o);
                float S2 = __shfl_xor_sync(0xffffffffu, S, o);
                unsigned long long k2 = __shfl_xor_sync(0xffffffffu, key, o);
                lse_merge(M, S, M2, S2);
                if (k2 > key) key = k2;
            }
            if (lane == 0) { s_wM[wib] = M; s_wS[wib] = S; s_wK[wib] = key; }
            __syncthreads();
            if (wib == 0) {
                M = s_wM[lane]; S = s_wS[lane]; key = s_wK[lane];
#pragma unroll
                for (int o = 16; o; o >>= 1) {
                    float M2 = __shfl_xor_sync(0xffffffffu, M, o);
                    float S2 = __shfl_xor_sync(0xffffffffu, S, o);
                    unsigned long long k2 = __shfl_xor_sync(0xffffffffu, key, o);
                    lse_merge(M, S, M2, S2);
                    if (k2 > key) key = k2;
                }
                if (lane == 0) {
                    d_pMs[step * NB + b] = M;
                    d_pSs[step * NB + b] = S;
                    d_pKs[step * NB + b] = key;
                    __threadfence();
                    *((volatile unsigned*)&d_donev[(step * NB + b) * 8]) = 1u;
                }
            }
        }
    }
}

// ---------------- host launcher ----------------
extern "C" void kernel_launch(void* const* d_in, const int* in_sizes, int n_in,
                              void* d_out, int out_size) {
    const float* state = (const float*)d_in[0];
    const float* model = (const float*)d_in[1];
    const int*   ei    = (const int*)d_in[2];
    const float* W_l   = (const float*)d_in[3];
    const float* W_r   = (const float*)d_in[4];
    const float* att   = (const float*)d_in[5];
    const float* cbias = (const float*)d_in[6];
    const float* Wih   = (const float*)d_in[7];
    const float* Whh   = (const float*)d_in[8];
    const float* bih   = (const float*)d_in[9];
    const float* bhh   = (const float*)d_in[10];
    const float* pW1   = (const float*)d_in[11];
    const float* pb1   = (const float*)d_in[12];
    const float* pW2   = (const float*)d_in[13];
    const float* pb2   = (const float*)d_in[14];
    const float* emb   = (const float*)d_in[15];
    float* out = (float*)d_out;

    setup_kernel<<<(HORn * NMn + 255) / 256, 256>>>();
    gemm_both<<<NBLK_NS + NBLK_NM, 256>>>(state, model, W_l, W_r);
    edge_score_exp<<<2048, 256>>>(ei, att);
    policy_kernel<<<NB, PTH>>>(ei, cbias, Wih, Whh, bih, bhh,
                               pW1, pb1, pW2, pb2, emb, out, out_size);
}